// round 2
// baseline (speedup 1.0000x reference)
#include <cuda_runtime.h>
#include <math.h>
#include <math_constants.h>

// ---------------------------------------------------------------------------
// CircleLoss fused kernel, round 1 (fp32 FFMA, fused masked LSE).
// Fix vs R0: labels are int32 (JAX x64 disabled downcasts int64 -> int32);
// reading them as int64 scrambled the pos/neg masks (rel_err 1.09e-1).
// ---------------------------------------------------------------------------

#define N_MAX   8192
#define D_DIM   256
#define BM      128
#define BN      128
#define BK      8
#define LDSA    132          // padded smem stride (kills bank conflicts, keeps 16B align)
#define NTHREADS 256
#define GAMMA   256.0f
#define DELTA_P 0.75f        // 1 - m
#define DELTA_N 0.25f        // m
#define OPT_P   1.25f        // 1 + m
#define OPT_N   0.25f        // m

// scratch (allocation-free: __device__ globals)
__device__ float g_x[(size_t)N_MAX * D_DIM];                       // normalized embeddings, 8 MB
__device__ float g_part[(N_MAX / BM) * (N_MAX / BN) * 4];          // per-block (mp,sp,mn,sn)

// ---------------------------------------------------------------------------
// Kernel 1: L2-normalize each row. One block (256 thr) per row, D == 256.
// ---------------------------------------------------------------------------
__global__ void normalize_kernel(const float* __restrict__ e, int D) {
    const int row = blockIdx.x;
    const int t   = threadIdx.x;
    const float v = e[(size_t)row * D + t];
    float ss = v * v;
    #pragma unroll
    for (int o = 16; o > 0; o >>= 1) ss += __shfl_xor_sync(0xffffffffu, ss, o);
    __shared__ float wsum[8];
    if ((t & 31) == 0) wsum[t >> 5] = ss;
    __syncthreads();
    float tot = 0.f;
    #pragma unroll
    for (int w = 0; w < 8; w++) tot += wsum[w];
    const float n = fmaxf(sqrtf(tot), 1e-12f);
    g_x[(size_t)row * D + t] = v / n;
}

// numerically-safe (m, s) logsumexp pair combine; invariant: m==-inf => s==0
__device__ __forceinline__ void lse_combine(float& m, float& s, float m2, float s2) {
    const float M = fmaxf(m, m2);
    if (M == -CUDART_INF_F) return;                    // both empty
    s = s * __expf(m - M) + s2 * __expf(m2 - M);       // exp(-inf - M) == 0
    m = M;
}

// ---------------------------------------------------------------------------
// Kernel 2: 128x128 tile of sim via register-blocked SGEMM (8x8 microtile),
// fused circle-loss logits + masked logsumexp, block-reduced to g_part.
// ---------------------------------------------------------------------------
__global__ __launch_bounds__(NTHREADS, 2)
void circle_tile_kernel(const int* __restrict__ labels, int N, int K) {
    __shared__ float As[BK][LDSA];
    __shared__ float Bs[BK][LDSA];
    __shared__ int   La[BM];
    __shared__ int   Lb[BN];
    __shared__ float rm[NTHREADS];
    __shared__ float rs[NTHREADS];

    const int tid = threadIdx.x;
    const int tx  = tid & 15;          // 16 cols of threads
    const int ty  = tid >> 4;          // 16 rows of threads
    const int rowBase = blockIdx.y * BM;
    const int colBase = blockIdx.x * BN;

    if (tid < BM) La[tid]      = labels[rowBase + tid];
    else          Lb[tid - BM] = labels[colBase + (tid - BM)];

    float acc[8][8];
    #pragma unroll
    for (int i = 0; i < 8; i++)
        #pragma unroll
        for (int j = 0; j < 8; j++) acc[i][j] = 0.f;

    // loader mapping: 256 threads move 128 rows x 8 k-cols as one float4 each
    const int lr = tid >> 1;                 // tile row 0..127
    const int kc = (tid & 1) * 4;            // k sub-offset 0 or 4
    const float* __restrict__ Aptr = g_x + (size_t)(rowBase + lr) * K + kc;
    const float* __restrict__ Bptr = g_x + (size_t)(colBase + lr) * K + kc;

    for (int k0 = 0; k0 < K; k0 += BK) {
        const float4 av = *(const float4*)(Aptr + k0);
        const float4 bv = *(const float4*)(Bptr + k0);
        __syncthreads();                     // protect prior iteration's reads
        As[kc + 0][lr] = av.x; As[kc + 1][lr] = av.y;
        As[kc + 2][lr] = av.z; As[kc + 3][lr] = av.w;
        Bs[kc + 0][lr] = bv.x; Bs[kc + 1][lr] = bv.y;
        Bs[kc + 2][lr] = bv.z; Bs[kc + 3][lr] = bv.w;
        __syncthreads();

        #pragma unroll
        for (int k = 0; k < BK; k++) {
            float a[8], b[8];
            const float4 a0 = *(const float4*)(&As[k][ty * 8]);
            const float4 a1 = *(const float4*)(&As[k][ty * 8 + 4]);
            const float4 b0 = *(const float4*)(&Bs[k][tx * 8]);
            const float4 b1 = *(const float4*)(&Bs[k][tx * 8 + 4]);
            a[0]=a0.x; a[1]=a0.y; a[2]=a0.z; a[3]=a0.w;
            a[4]=a1.x; a[5]=a1.y; a[6]=a1.z; a[7]=a1.w;
            b[0]=b0.x; b[1]=b0.y; b[2]=b0.z; b[3]=b0.w;
            b[4]=b1.x; b[5]=b1.y; b[6]=b1.z; b[7]=b1.w;
            #pragma unroll
            for (int i = 0; i < 8; i++)
                #pragma unroll
                for (int j = 0; j < 8; j++)
                    acc[i][j] = fmaf(a[i], b[j], acc[i][j]);
        }
    }

    // ---- fused epilogue: logits in-place, two-pass masked LSE ----
    int li[8], lj[8];
    #pragma unroll
    for (int i = 0; i < 8; i++) { li[i] = La[ty * 8 + i]; lj[i] = Lb[tx * 8 + i]; }

    float mp = -CUDART_INF_F, mn = -CUDART_INF_F;
    #pragma unroll
    for (int i = 0; i < 8; i++) {
        const int gi = rowBase + ty * 8 + i;
        #pragma unroll
        for (int j = 0; j < 8; j++) {
            const int gj = colBase + tx * 8 + j;
            const float s  = acc[i][j];
            const bool pos = (li[i] == lj[j]);
            const float lp = -GAMMA * fmaxf(OPT_P - s, 0.f) * (s - DELTA_P);
            const float ln =  GAMMA * fmaxf(s + OPT_N, 0.f) * (s - DELTA_N);
            float lg = pos ? lp : ln;
            if (pos && gi == gj) lg = -CUDART_INF_F;    // exclude diagonal
            if (pos) mp = fmaxf(mp, lg);
            else     mn = fmaxf(mn, lg);
            acc[i][j] = lg;
        }
    }

    const float mpu = (mp < -1e37f) ? 0.f : mp;   // avoid -inf - -inf = NaN
    const float mnu = (mn < -1e37f) ? 0.f : mn;
    float sp = 0.f, sn = 0.f;
    #pragma unroll
    for (int i = 0; i < 8; i++) {
        #pragma unroll
        for (int j = 0; j < 8; j++) {
            const bool pos = (li[i] == lj[j]);
            const float e = __expf(acc[i][j] - (pos ? mpu : mnu));
            if (pos) sp += e; else sn += e;
        }
    }

    const int bid = blockIdx.y * gridDim.x + blockIdx.x;

    // block reduce positives
    rm[tid] = mp; rs[tid] = sp; __syncthreads();
    for (int off = NTHREADS / 2; off > 0; off >>= 1) {
        if (tid < off) {
            float m = rm[tid], s = rs[tid];
            lse_combine(m, s, rm[tid + off], rs[tid + off]);
            rm[tid] = m; rs[tid] = s;
        }
        __syncthreads();
    }
    if (tid == 0) { g_part[bid * 4 + 0] = rm[0]; g_part[bid * 4 + 1] = rs[0]; }
    __syncthreads();

    // block reduce negatives
    rm[tid] = mn; rs[tid] = sn; __syncthreads();
    for (int off = NTHREADS / 2; off > 0; off >>= 1) {
        if (tid < off) {
            float m = rm[tid], s = rs[tid];
            lse_combine(m, s, rm[tid + off], rs[tid + off]);
            rm[tid] = m; rs[tid] = s;
        }
        __syncthreads();
    }
    if (tid == 0) { g_part[bid * 4 + 2] = rm[0]; g_part[bid * 4 + 3] = rs[0]; }
}

// ---------------------------------------------------------------------------
// Kernel 3: combine all block partials, softplus, write scalar.
// ---------------------------------------------------------------------------
__global__ void finalize_kernel(float* __restrict__ out, int nPart) {
    const int t = threadIdx.x;
    float mp = -CUDART_INF_F, sp = 0.f, mn = -CUDART_INF_F, sn = 0.f;
    for (int i = t; i < nPart; i += blockDim.x) {
        lse_combine(mp, sp, g_part[i * 4 + 0], g_part[i * 4 + 1]);
        lse_combine(mn, sn, g_part[i * 4 + 2], g_part[i * 4 + 3]);
    }
    __shared__ float rm[256], rs[256];
    __shared__ float lse_p;

    rm[t] = mp; rs[t] = sp; __syncthreads();
    for (int off = 128; off > 0; off >>= 1) {
        if (t < off) {
            float m = rm[t], s = rs[t];
            lse_combine(m, s, rm[t + off], rs[t + off]);
            rm[t] = m; rs[t] = s;
        }
        __syncthreads();
    }
    if (t == 0) lse_p = rm[0] + logf(rs[0]);
    __syncthreads();

    rm[t] = mn; rs[t] = sn; __syncthreads();
    for (int off = 128; off > 0; off >>= 1) {
        if (t < off) {
            float m = rm[t], s = rs[t];
            lse_combine(m, s, rm[t + off], rs[t + off]);
            rm[t] = m; rs[t] = s;
        }
        __syncthreads();
    }
    if (t == 0) {
        const float x = lse_p + rm[0] + logf(rs[0]);
        out[0] = (x > 20.f) ? x : log1pf(expf(x));   // softplus
    }
}

// ---------------------------------------------------------------------------
extern "C" void kernel_launch(void* const* d_in, const int* in_sizes, int n_in,
                              void* d_out, int out_size) {
    const float* emb    = (const float*)d_in[0];
    const int*   labels = (const int*)d_in[1];     // int32 (JAX x64 off)
    float*       out    = (float*)d_out;

    const int B = in_sizes[1];            // 8192
    const int D = in_sizes[0] / B;        // 256

    normalize_kernel<<<B, D>>>(emb, D);

    dim3 grid(B / BN, B / BM);
    circle_tile_kernel<<<grid, NTHREADS>>>(labels, B, D);

    finalize_kernel<<<1, 256>>>(out, (B / BM) * (B / BN));
}

// round 3
// speedup vs baseline: 1.8009x; 1.8009x over previous
#include <cuda_runtime.h>
#include <math.h>
#include <math_constants.h>

// ---------------------------------------------------------------------------
// CircleLoss fused kernel, round 2: symmetric-tile version.
//   sim is symmetric and the logit depends only on (sim, same-label), so
//   LSE(full) == LSE(upper tiles) with off-diagonal tile sums doubled.
//   Tiles: 64*65/2 = 2080 instead of 4096  ->  ~0.508x FMA + exp work.
// ---------------------------------------------------------------------------

#define N_MAX   8192
#define D_DIM   256
#define BM      128
#define BN      128
#define BK      8
#define LDSA    132          // padded smem stride (conflict-free, 16B aligned)
#define NTHREADS 256
#define NB      (N_MAX / BM) // 64 tile-rows
#define NTILES  (NB * (NB + 1) / 2)
#define GAMMA   256.0f
#define DELTA_P 0.75f        // 1 - m
#define DELTA_N 0.25f        // m
#define OPT_P   1.25f        // 1 + m
#define OPT_N   0.25f        // m

// scratch (allocation-free: __device__ globals)
__device__ float g_x[(size_t)N_MAX * D_DIM];     // normalized embeddings, 8 MB
__device__ float g_part[NTILES * 4];             // per-block (mp,sp,mn,sn)

// ---------------------------------------------------------------------------
// Kernel 1: L2-normalize each row. One block (256 thr) per row, D == 256.
// ---------------------------------------------------------------------------
__global__ void normalize_kernel(const float* __restrict__ e, int D) {
    const int row = blockIdx.x;
    const int t   = threadIdx.x;
    const float v = e[(size_t)row * D + t];
    float ss = v * v;
    #pragma unroll
    for (int o = 16; o > 0; o >>= 1) ss += __shfl_xor_sync(0xffffffffu, ss, o);
    __shared__ float wsum[8];
    if ((t & 31) == 0) wsum[t >> 5] = ss;
    __syncthreads();
    float tot = 0.f;
    #pragma unroll
    for (int w = 0; w < 8; w++) tot += wsum[w];
    const float n = fmaxf(sqrtf(tot), 1e-12f);
    g_x[(size_t)row * D + t] = v / n;
}

// numerically-safe (m, s) logsumexp pair combine; invariant: m==-inf => s==0
__device__ __forceinline__ void lse_combine(float& m, float& s, float m2, float s2) {
    const float M = fmaxf(m, m2);
    if (M == -CUDART_INF_F) return;                    // both empty
    s = s * __expf(m - M) + s2 * __expf(m2 - M);       // exp(-inf - M) == 0
    m = M;
}

// ---------------------------------------------------------------------------
// Kernel 2: one upper-triangle 128x128 tile of sim per block.
// Register-blocked SGEMM (8x8 microtile) + fused masked LSE.
// Off-diagonal tiles contribute their sum-exp twice (symmetry).
// ---------------------------------------------------------------------------
__global__ __launch_bounds__(NTHREADS, 2)
void circle_tile_kernel(const int* __restrict__ labels, int K) {
    __shared__ float As[BK][LDSA];
    __shared__ float Bs[BK][LDSA];
    __shared__ int   La[BM];
    __shared__ int   Lb[BN];
    __shared__ float rm[NTHREADS];
    __shared__ float rs[NTHREADS];

    // map linear tile id -> (bi, bj) with bj >= bi (row-major upper triangle)
    int t = blockIdx.x;
    int bi = 0;
    int rowLen = NB;
    while (t >= rowLen) { t -= rowLen; rowLen--; bi++; }
    const int bj = bi + t;
    const float tileW = (bi == bj) ? 1.0f : 2.0f;

    const int tid = threadIdx.x;
    const int tx  = tid & 15;          // 16 cols of threads
    const int ty  = tid >> 4;          // 16 rows of threads
    const int rowBase = bi * BM;
    const int colBase = bj * BN;

    if (tid < BM) La[tid]      = labels[rowBase + tid];
    else          Lb[tid - BM] = labels[colBase + (tid - BM)];

    float acc[8][8];
    #pragma unroll
    for (int i = 0; i < 8; i++)
        #pragma unroll
        for (int j = 0; j < 8; j++) acc[i][j] = 0.f;

    // loader mapping: 256 threads move 128 rows x 8 k-cols as one float4 each
    const int lr = tid >> 1;                 // tile row 0..127
    const int kc = (tid & 1) * 4;            // k sub-offset 0 or 4
    const float* __restrict__ Aptr = g_x + (size_t)(rowBase + lr) * K + kc;
    const float* __restrict__ Bptr = g_x + (size_t)(colBase + lr) * K + kc;

    for (int k0 = 0; k0 < K; k0 += BK) {
        const float4 av = *(const float4*)(Aptr + k0);
        const float4 bv = *(const float4*)(Bptr + k0);
        __syncthreads();                     // protect prior iteration's reads
        As[kc + 0][lr] = av.x; As[kc + 1][lr] = av.y;
        As[kc + 2][lr] = av.z; As[kc + 3][lr] = av.w;
        Bs[kc + 0][lr] = bv.x; Bs[kc + 1][lr] = bv.y;
        Bs[kc + 2][lr] = bv.z; Bs[kc + 3][lr] = bv.w;
        __syncthreads();

        #pragma unroll
        for (int k = 0; k < BK; k++) {
            float a[8], b[8];
            const float4 a0 = *(const float4*)(&As[k][ty * 8]);
            const float4 a1 = *(const float4*)(&As[k][ty * 8 + 4]);
            const float4 b0 = *(const float4*)(&Bs[k][tx * 8]);
            const float4 b1 = *(const float4*)(&Bs[k][tx * 8 + 4]);
            a[0]=a0.x; a[1]=a0.y; a[2]=a0.z; a[3]=a0.w;
            a[4]=a1.x; a[5]=a1.y; a[6]=a1.z; a[7]=a1.w;
            b[0]=b0.x; b[1]=b0.y; b[2]=b0.z; b[3]=b0.w;
            b[4]=b1.x; b[5]=b1.y; b[6]=b1.z; b[7]=b1.w;
            #pragma unroll
            for (int i = 0; i < 8; i++)
                #pragma unroll
                for (int j = 0; j < 8; j++)
                    acc[i][j] = fmaf(a[i], b[j], acc[i][j]);
        }
    }

    // ---- fused epilogue: logits in-place, two-pass masked LSE ----
    int li[8], lj[8];
    #pragma unroll
    for (int i = 0; i < 8; i++) { li[i] = La[ty * 8 + i]; lj[i] = Lb[tx * 8 + i]; }

    float mp = -CUDART_INF_F, mn = -CUDART_INF_F;
    #pragma unroll
    for (int i = 0; i < 8; i++) {
        const int gi = rowBase + ty * 8 + i;
        #pragma unroll
        for (int j = 0; j < 8; j++) {
            const int gj = colBase + tx * 8 + j;
            const float s  = acc[i][j];
            const bool pos = (li[i] == lj[j]);
            const float lp = -GAMMA * fmaxf(OPT_P - s, 0.f) * (s - DELTA_P);
            const float ln =  GAMMA * fmaxf(s + OPT_N, 0.f) * (s - DELTA_N);
            float lg = pos ? lp : ln;
            if (pos && gi == gj) lg = -CUDART_INF_F;    // exclude diagonal
            if (pos) mp = fmaxf(mp, lg);
            else     mn = fmaxf(mn, lg);
            acc[i][j] = lg;
        }
    }

    const float mpu = (mp < -1e37f) ? 0.f : mp;   // avoid -inf - -inf = NaN
    const float mnu = (mn < -1e37f) ? 0.f : mn;
    float sp = 0.f, sn = 0.f;
    #pragma unroll
    for (int i = 0; i < 8; i++) {
        #pragma unroll
        for (int j = 0; j < 8; j++) {
            const bool pos = (li[i] == lj[j]);
            const float e = __expf(acc[i][j] - (pos ? mpu : mnu));
            if (pos) sp += e; else sn += e;
        }
    }
    // symmetry weight: off-diagonal tiles count twice (exact scaling of s)
    sp *= tileW;
    sn *= tileW;

    const int bid = blockIdx.x;

    // block reduce positives
    rm[tid] = mp; rs[tid] = sp; __syncthreads();
    for (int off = NTHREADS / 2; off > 0; off >>= 1) {
        if (tid < off) {
            float m = rm[tid], s = rs[tid];
            lse_combine(m, s, rm[tid + off], rs[tid + off]);
            rm[tid] = m; rs[tid] = s;
        }
        __syncthreads();
    }
    if (tid == 0) { g_part[bid * 4 + 0] = rm[0]; g_part[bid * 4 + 1] = rs[0]; }
    __syncthreads();

    // block reduce negatives
    rm[tid] = mn; rs[tid] = sn; __syncthreads();
    for (int off = NTHREADS / 2; off > 0; off >>= 1) {
        if (tid < off) {
            float m = rm[tid], s = rs[tid];
            lse_combine(m, s, rm[tid + off], rs[tid + off]);
            rm[tid] = m; rs[tid] = s;
        }
        __syncthreads();
    }
    if (tid == 0) { g_part[bid * 4 + 2] = rm[0]; g_part[bid * 4 + 3] = rs[0]; }
}

// ---------------------------------------------------------------------------
// Kernel 3: combine all block partials, softplus, write scalar.
// ---------------------------------------------------------------------------
__global__ void finalize_kernel(float* __restrict__ out, int nPart) {
    const int t = threadIdx.x;
    float mp = -CUDART_INF_F, sp = 0.f, mn = -CUDART_INF_F, sn = 0.f;
    for (int i = t; i < nPart; i += blockDim.x) {
        lse_combine(mp, sp, g_part[i * 4 + 0], g_part[i * 4 + 1]);
        lse_combine(mn, sn, g_part[i * 4 + 2], g_part[i * 4 + 3]);
    }
    __shared__ float rm[256], rs[256];
    __shared__ float lse_p;

    rm[t] = mp; rs[t] = sp; __syncthreads();
    for (int off = 128; off > 0; off >>= 1) {
        if (t < off) {
            float m = rm[t], s = rs[t];
            lse_combine(m, s, rm[t + off], rs[t + off]);
            rm[t] = m; rs[t] = s;
        }
        __syncthreads();
    }
    if (t == 0) lse_p = rm[0] + logf(rs[0]);
    __syncthreads();

    rm[t] = mn; rs[t] = sn; __syncthreads();
    for (int off = 128; off > 0; off >>= 1) {
        if (t < off) {
            float m = rm[t], s = rs[t];
            lse_combine(m, s, rm[t + off], rs[t + off]);
            rm[t] = m; rs[t] = s;
        }
        __syncthreads();
    }
    if (t == 0) {
        const float x = lse_p + rm[0] + logf(rs[0]);
        out[0] = (x > 20.f) ? x : log1pf(expf(x));   // softplus
    }
}

// ---------------------------------------------------------------------------
extern "C" void kernel_launch(void* const* d_in, const int* in_sizes, int n_in,
                              void* d_out, int out_size) {
    const float* emb    = (const float*)d_in[0];
    const int*   labels = (const int*)d_in[1];     // int32 (JAX x64 off)
    float*       out    = (float*)d_out;

    const int B = in_sizes[1];            // 8192
    const int D = in_sizes[0] / B;        // 256

    normalize_kernel<<<B, D>>>(emb, D);

    circle_tile_kernel<<<NTILES, NTHREADS>>>(labels, D);

    finalize_kernel<<<1, 256>>>(out, NTILES);
}

// round 5
// speedup vs baseline: 4.5347x; 2.5180x over previous
#include <cuda_runtime.h>
#include <cuda_bf16.h>
#include <math.h>
#include <math_constants.h>
#include <stdint.h>

// ---------------------------------------------------------------------------
// CircleLoss round 4: split-bf16 mma.sync (HMMA) GEMM + fused masked LSE.
//   tcgen05 unavailable (harness targets sm_100, not sm_100a).
//   sim = hi.hi^T + hi.lo^T + lo.hi^T  (lo.lo dropped, ~4e-6 abs)
//   Upper-triangle tiles; off-diagonal sum-exp doubled (exact).
// ---------------------------------------------------------------------------

#define N_MAX    8192
#define D_DIM    256
#define BM       128
#define BN       128
#define NB       (N_MAX / BM)          // 64
#define NTILES   (NB * (NB + 1) / 2)   // 2080
#define NTHREADS 256
#define CHK      64                    // K-chunk (bf16 elems)
#define NCH      (D_DIM / CHK)         // 4
#define SSTRIDE  72                    // padded smem row stride (elems)
#define BUF_B    (BM * SSTRIDE * 2)    // 18432 bytes per buffer
#define GAMMA    256.0f
#define DELTA_P  0.75f
#define DELTA_N  0.25f
#define OPT_P    1.25f
#define OPT_N    0.25f

__device__ __nv_bfloat16 g_xhi[(size_t)N_MAX * D_DIM];   // 4 MB
__device__ __nv_bfloat16 g_xlo[(size_t)N_MAX * D_DIM];   // 4 MB
__device__ float         g_part[NTILES * 4];

__device__ __forceinline__ uint32_t smem_u32(const void* p) {
    uint32_t a;
    asm("{ .reg .u64 t; cvta.to.shared.u64 t, %1; cvt.u32.u64 %0, t; }" : "=r"(a) : "l"(p));
    return a;
}
__device__ __forceinline__ void ldm_x4(uint32_t* f, uint32_t addr) {
    asm volatile("ldmatrix.sync.aligned.m8n8.x4.shared.b16 {%0,%1,%2,%3}, [%4];"
                 : "=r"(f[0]), "=r"(f[1]), "=r"(f[2]), "=r"(f[3]) : "r"(addr));
}
__device__ __forceinline__ void ldm_x2(uint32_t* f, uint32_t addr) {
    asm volatile("ldmatrix.sync.aligned.m8n8.x2.shared.b16 {%0,%1}, [%2];"
                 : "=r"(f[0]), "=r"(f[1]) : "r"(addr));
}
__device__ __forceinline__ void mma_bf16(float* d, const uint32_t* a, const uint32_t* b) {
    asm volatile("mma.sync.aligned.m16n8k16.row.col.f32.bf16.bf16.f32 "
                 "{%0,%1,%2,%3}, {%4,%5,%6,%7}, {%8,%9}, {%0,%1,%2,%3};"
                 : "+f"(d[0]), "+f"(d[1]), "+f"(d[2]), "+f"(d[3])
                 : "r"(a[0]), "r"(a[1]), "r"(a[2]), "r"(a[3]), "r"(b[0]), "r"(b[1]));
}
__device__ __forceinline__ void sts128(uint32_t addr, uint4 v) {
    asm volatile("st.shared.v4.b32 [%0], {%1,%2,%3,%4};"
                 :: "r"(addr), "r"(v.x), "r"(v.y), "r"(v.z), "r"(v.w) : "memory");
}

// ---------------------------------------------------------------------------
// Kernel 1: L2-normalize + split into bf16 hi/lo.
// ---------------------------------------------------------------------------
__global__ void normalize_kernel(const float* __restrict__ e, int D) {
    const int row = blockIdx.x;
    const int t   = threadIdx.x;
    const float v = e[(size_t)row * D + t];
    float ss = v * v;
    #pragma unroll
    for (int o = 16; o > 0; o >>= 1) ss += __shfl_xor_sync(0xffffffffu, ss, o);
    __shared__ float wsum[8];
    if ((t & 31) == 0) wsum[t >> 5] = ss;
    __syncthreads();
    float tot = 0.f;
    #pragma unroll
    for (int w = 0; w < 8; w++) tot += wsum[w];
    const float n = fmaxf(sqrtf(tot), 1e-12f);
    const float x = v / n;
    const __nv_bfloat16 hi = __float2bfloat16(x);
    const __nv_bfloat16 lo = __float2bfloat16(x - __bfloat162float(hi));
    g_xhi[(size_t)row * D + t] = hi;
    g_xlo[(size_t)row * D + t] = lo;
}

__device__ __forceinline__ void lse_combine(float& m, float& s, float m2, float s2) {
    const float M = fmaxf(m, m2);
    if (M == -CUDART_INF_F) return;
    s = s * __expf(m - M) + s2 * __expf(m2 - M);
    m = M;
}

// ---------------------------------------------------------------------------
// Kernel 2: one upper-triangle 128x128 tile per block; 8 warps in a 2x4 grid,
// each warp computes a 64x32 sub-tile via mma.sync m16n8k16 bf16 (3 products).
// ---------------------------------------------------------------------------
__global__ __launch_bounds__(NTHREADS, 2)
void circle_tile_mma(const int* __restrict__ labels) {
    extern __shared__ char dsm[];
    __shared__ int   La[BM];
    __shared__ int   Lb[BN];
    __shared__ float rm[NTHREADS];
    __shared__ float rs[NTHREADS];

    const int tid  = threadIdx.x;
    const int wid  = tid >> 5;
    const int lane = tid & 31;
    const int wm   = wid & 1;          // warp row   (0..1) -> 64 rows
    const int wn   = wid >> 1;         // warp col   (0..3) -> 32 cols

    const uint32_t sb  = smem_u32(dsm);
    const uint32_t Ahi = sb, Alo = sb + BUF_B, Bhi = sb + 2 * BUF_B, Blo = sb + 3 * BUF_B;

    // tile id -> (bi, bj), bj >= bi
    int t = blockIdx.x, bi = 0, rowLen = NB;
    while (t >= rowLen) { t -= rowLen; rowLen--; bi++; }
    const int bj = bi + t;
    const float tileW = (bi == bj) ? 1.0f : 2.0f;
    const int rowBase = bi * BM, colBase = bj * BN;

    if (tid < BM) La[tid]      = labels[rowBase + tid];
    else          Lb[tid - BM] = labels[colBase + (tid - BM)];

    float acc[4][4][4];
    #pragma unroll
    for (int mi = 0; mi < 4; mi++)
        #pragma unroll
        for (int ni = 0; ni < 4; ni++)
            #pragma unroll
            for (int e = 0; e < 4; e++) acc[mi][ni][e] = 0.f;

    const uint4* __restrict__ phi = (const uint4*)g_xhi;
    const uint4* __restrict__ plo = (const uint4*)g_xlo;

    // per-lane ldmatrix address offsets (within a 16x16 / 8x16 fragment)
    const int arow = (lane & 7) + ((lane >> 3) & 1) * 8;   // A: 0..15
    const int acol = (lane >> 4) * 8;                      // A: 0 or 8
    const int brow = lane & 7;                             // B: 0..7
    const int bcol = ((lane >> 3) & 1) * 8;                // B: 0 or 8 (lanes 0-15 used)

    for (int c = 0; c < NCH; c++) {
        __syncthreads();
        // stage 4 buffers: 4 x (128 rows x 8 uint4); each thread stores 16 uint4
        #pragma unroll
        for (int it = 0; it < 16; it++) {
            const int idx = tid + it * NTHREADS;
            const int buf = idx >> 10;            // 0:Ahi 1:Alo 2:Bhi 3:Blo
            const int v   = idx & 1023;
            const int r   = v >> 3;
            const int cg  = v & 7;
            const int grow = ((buf < 2) ? rowBase : colBase) + r;
            const uint4 val = ((buf & 1) ? plo : phi)[grow * 32 + c * 8 + cg];
            const uint32_t base = (buf == 0) ? Ahi : (buf == 1) ? Alo : (buf == 2) ? Bhi : Blo;
            sts128(base + (uint32_t)(r * SSTRIDE + cg * 8) * 2, val);
        }
        __syncthreads();

        #pragma unroll
        for (int ks = 0; ks < CHK / 16; ks++) {
            const int k0 = ks * 16;
            uint32_t af[4][4], bh[4][2], bl[4][2];
            #pragma unroll
            for (int mi = 0; mi < 4; mi++) {
                const int r = wm * 64 + mi * 16 + arow;
                ldm_x4(af[mi], Ahi + (uint32_t)(r * SSTRIDE + k0 + acol) * 2);
            }
            #pragma unroll
            for (int ni = 0; ni < 4; ni++) {
                const int r = wn * 32 + ni * 8 + brow;
                const uint32_t off = (uint32_t)(r * SSTRIDE + k0 + bcol) * 2;
                ldm_x2(bh[ni], Bhi + off);
                ldm_x2(bl[ni], Blo + off);
            }
            #pragma unroll
            for (int mi = 0; mi < 4; mi++)
                #pragma unroll
                for (int ni = 0; ni < 4; ni++) {
                    mma_bf16(acc[mi][ni], af[mi], bh[ni]);   // hi . hi
                    mma_bf16(acc[mi][ni], af[mi], bl[ni]);   // hi . lo
                }
            // reload A as lo, reuse bh
            #pragma unroll
            for (int mi = 0; mi < 4; mi++) {
                const int r = wm * 64 + mi * 16 + arow;
                ldm_x4(af[mi], Alo + (uint32_t)(r * SSTRIDE + k0 + acol) * 2);
            }
            #pragma unroll
            for (int mi = 0; mi < 4; mi++)
                #pragma unroll
                for (int ni = 0; ni < 4; ni++)
                    mma_bf16(acc[mi][ni], af[mi], bh[ni]);   // lo . hi
        }
    }

    // ---- fused epilogue on register fragments ----
    // element (mi,ni,e): row = wm*64 + mi*16 + lane/4 + (e>>1)*8
    //                    col = wn*32 + ni*8  + (lane%4)*2 + (e&1)
    int liA[8], ljB[8];
    #pragma unroll
    for (int mi = 0; mi < 4; mi++) {
        liA[mi * 2]     = La[wm * 64 + mi * 16 + (lane >> 2)];
        liA[mi * 2 + 1] = La[wm * 64 + mi * 16 + (lane >> 2) + 8];
    }
    #pragma unroll
    for (int ni = 0; ni < 4; ni++) {
        ljB[ni * 2]     = Lb[wn * 32 + ni * 8 + (lane & 3) * 2];
        ljB[ni * 2 + 1] = Lb[wn * 32 + ni * 8 + (lane & 3) * 2 + 1];
    }

    float mp = -CUDART_INF_F, mn = -CUDART_INF_F;
    #pragma unroll
    for (int mi = 0; mi < 4; mi++)
        #pragma unroll
        for (int ni = 0; ni < 4; ni++)
            #pragma unroll
            for (int e = 0; e < 4; e++) {
                const int row = wm * 64 + mi * 16 + (lane >> 2) + (e >> 1) * 8;
                const int col = wn * 32 + ni * 8 + (lane & 3) * 2 + (e & 1);
                const float s = acc[mi][ni][e];
                const bool pos = (liA[mi * 2 + (e >> 1)] == ljB[ni * 2 + (e & 1)]);
                const float lp = -GAMMA * fmaxf(OPT_P - s, 0.f) * (s - DELTA_P);
                const float ln =  GAMMA * fmaxf(s + OPT_N, 0.f) * (s - DELTA_N);
                float l = pos ? lp : ln;
                if (pos && (rowBase + row) == (colBase + col)) l = -CUDART_INF_F;
                if (pos) mp = fmaxf(mp, l); else mn = fmaxf(mn, l);
                acc[mi][ni][e] = l;
            }

    const float mpu = (mp < -1e37f) ? 0.f : mp;
    const float mnu = (mn < -1e37f) ? 0.f : mn;
    float sp = 0.f, sn = 0.f;
    #pragma unroll
    for (int mi = 0; mi < 4; mi++)
        #pragma unroll
        for (int ni = 0; ni < 4; ni++)
            #pragma unroll
            for (int e = 0; e < 4; e++) {
                const bool pos = (liA[mi * 2 + (e >> 1)] == ljB[ni * 2 + (e & 1)]);
                const float ex = __expf(acc[mi][ni][e] - (pos ? mpu : mnu));
                if (pos) sp += ex; else sn += ex;
            }
    sp *= tileW; sn *= tileW;

    const int bid = blockIdx.x;
    rm[tid] = mp; rs[tid] = sp; __syncthreads();
    for (int off = NTHREADS / 2; off > 0; off >>= 1) {
        if (tid < off) {
            float m = rm[tid], s = rs[tid];
            lse_combine(m, s, rm[tid + off], rs[tid + off]);
            rm[tid] = m; rs[tid] = s;
        }
        __syncthreads();
    }
    if (tid == 0) { g_part[bid * 4 + 0] = rm[0]; g_part[bid * 4 + 1] = rs[0]; }
    __syncthreads();
    rm[tid] = mn; rs[tid] = sn; __syncthreads();
    for (int off = NTHREADS / 2; off > 0; off >>= 1) {
        if (tid < off) {
            float m = rm[tid], s = rs[tid];
            lse_combine(m, s, rm[tid + off], rs[tid + off]);
            rm[tid] = m; rs[tid] = s;
        }
        __syncthreads();
    }
    if (tid == 0) { g_part[bid * 4 + 2] = rm[0]; g_part[bid * 4 + 3] = rs[0]; }
}

// ---------------------------------------------------------------------------
// Kernel 3: combine partials, softplus, write scalar.
// ---------------------------------------------------------------------------
__global__ void finalize_kernel(float* __restrict__ out, int nPart) {
    const int t = threadIdx.x;
    float mp = -CUDART_INF_F, sp = 0.f, mn = -CUDART_INF_F, sn = 0.f;
    for (int i = t; i < nPart; i += blockDim.x) {
        lse_combine(mp, sp, g_part[i * 4 + 0], g_part[i * 4 + 1]);
        lse_combine(mn, sn, g_part[i * 4 + 2], g_part[i * 4 + 3]);
    }
    __shared__ float rm[256], rs[256];
    __shared__ float lse_p;
    rm[t] = mp; rs[t] = sp; __syncthreads();
    for (int off = 128; off > 0; off >>= 1) {
        if (t < off) {
            float m = rm[t], s = rs[t];
            lse_combine(m, s, rm[t + off], rs[t + off]);
            rm[t] = m; rs[t] = s;
        }
        __syncthreads();
    }
    if (t == 0) lse_p = rm[0] + logf(rs[0]);
    __syncthreads();
    rm[t] = mn; rs[t] = sn; __syncthreads();
    for (int off = 128; off > 0; off >>= 1) {
        if (t < off) {
            float m = rm[t], s = rs[t];
            lse_combine(m, s, rm[t + off], rs[t + off]);
            rm[t] = m; rs[t] = s;
        }
        __syncthreads();
    }
    if (t == 0) {
        const float x = lse_p + rm[0] + logf(rs[0]);
        out[0] = (x > 20.f) ? x : log1pf(expf(x));
    }
}

// ---------------------------------------------------------------------------
extern "C" void kernel_launch(void* const* d_in, const int* in_sizes, int n_in,
                              void* d_out, int out_size) {
    const float* emb    = (const float*)d_in[0];
    const int*   labels = (const int*)d_in[1];
    float*       out    = (float*)d_out;

    const int B = in_sizes[1];            // 8192
    const int D = in_sizes[0] / B;        // 256
    const int dyn = 4 * BUF_B;            // 73728 bytes

    cudaFuncSetAttribute(circle_tile_mma, cudaFuncAttributeMaxDynamicSharedMemorySize, dyn);

    normalize_kernel<<<B, D>>>(emb, D);
    circle_tile_mma<<<NTILES, NTHREADS, dyn>>>(labels);
    finalize_kernel<<<1, 256>>>(out, NTILES);
}

// round 6
// speedup vs baseline: 4.8806x; 1.0763x over previous
#include <cuda_runtime.h>
#include <math.h>
#include <math_constants.h>
#include <stdint.h>

// ---------------------------------------------------------------------------
// CircleLoss round 5: int8 IMMA (m16n8k32) 2-digit quantized GEMM + fused LSE.
//   x ~= a*q + b*q^2, q=1/127.  sim = q^2(a.a') + q^3(a.b' + b.a')  [exact int]
//   b.b' (q^4) dropped: rms ~8e-5.  Upper-triangle tiles, off-diag doubled.
//   cp.async double-buffered staging; 1 CTA/SM (high reg count).
// ---------------------------------------------------------------------------

#define N_MAX    8192
#define D_DIM    256
#define BM       128
#define BN       128
#define NB       (N_MAX / BM)          // 64
#define NTILES   (NB * (NB + 1) / 2)   // 2080
#define NTHREADS 256
#define CHK      64                    // K-chunk (int8 elems = bytes)
#define NCH      (D_DIM / CHK)         // 4
#define STRIDE   80                    // smem row stride bytes (64 + 16 pad)
#define BUF_B    (BM * STRIDE)         // 10240 per buffer
#define STAGE_B  (4 * BUF_B)           // Aa, Ab, Ba, Bb
#define GAMMA    256.0f
#define DELTA_P  0.75f
#define DELTA_N  0.25f
#define OPT_P    1.25f
#define OPT_N    0.25f

#define QF   (1.0f / 127.0f)
#define Q2F  (QF * QF)
#define Q3F  (QF * QF * QF)

__device__ char  g_qa[(size_t)N_MAX * D_DIM];   // 2 MB digit-1
__device__ char  g_qb[(size_t)N_MAX * D_DIM];   // 2 MB digit-2
__device__ float g_part[NTILES * 4];

__device__ __forceinline__ uint32_t smem_u32(const void* p) {
    uint32_t a;
    asm("{ .reg .u64 t; cvta.to.shared.u64 t, %1; cvt.u32.u64 %0, t; }" : "=r"(a) : "l"(p));
    return a;
}
__device__ __forceinline__ void ldm_x4(uint32_t* f, uint32_t addr) {
    asm volatile("ldmatrix.sync.aligned.m8n8.x4.shared.b16 {%0,%1,%2,%3}, [%4];"
                 : "=r"(f[0]), "=r"(f[1]), "=r"(f[2]), "=r"(f[3]) : "r"(addr));
}
__device__ __forceinline__ void ldm_x2(uint32_t* f, uint32_t addr) {
    asm volatile("ldmatrix.sync.aligned.m8n8.x2.shared.b16 {%0,%1}, [%2];"
                 : "=r"(f[0]), "=r"(f[1]) : "r"(addr));
}
__device__ __forceinline__ void mma_s8(int* d, const uint32_t* a, const uint32_t* b) {
    asm volatile("mma.sync.aligned.m16n8k32.row.col.s32.s8.s8.s32 "
                 "{%0,%1,%2,%3}, {%4,%5,%6,%7}, {%8,%9}, {%0,%1,%2,%3};"
                 : "+r"(d[0]), "+r"(d[1]), "+r"(d[2]), "+r"(d[3])
                 : "r"(a[0]), "r"(a[1]), "r"(a[2]), "r"(a[3]), "r"(b[0]), "r"(b[1]));
}
__device__ __forceinline__ void cpasync16(uint32_t saddr, const void* g) {
    asm volatile("cp.async.cg.shared.global [%0], [%1], 16;" :: "r"(saddr), "l"(g) : "memory");
}
#define CP_COMMIT() asm volatile("cp.async.commit_group;" ::: "memory")
#define CP_WAIT1()  asm volatile("cp.async.wait_group 1;" ::: "memory")
#define CP_WAIT0()  asm volatile("cp.async.wait_group 0;" ::: "memory")

// ---------------------------------------------------------------------------
// Kernel 1: L2-normalize + 2-digit int8 quantize.
// ---------------------------------------------------------------------------
__global__ void quantize_kernel(const float* __restrict__ e, int D) {
    const int row = blockIdx.x;
    const int t   = threadIdx.x;
    const float v = e[(size_t)row * D + t];
    float ss = v * v;
    #pragma unroll
    for (int o = 16; o > 0; o >>= 1) ss += __shfl_xor_sync(0xffffffffu, ss, o);
    __shared__ float wsum[8];
    if ((t & 31) == 0) wsum[t >> 5] = ss;
    __syncthreads();
    float tot = 0.f;
    #pragma unroll
    for (int w = 0; w < 8; w++) tot += wsum[w];
    const float n = fmaxf(sqrtf(tot), 1e-12f);
    const float x = v / n;                       // |x| <= 1
    const float xa = x * 127.0f;
    const float a  = rintf(xa);                  // [-127, 127]
    const float b  = rintf((xa - a) * 127.0f);   // [-64, 64]
    g_qa[(size_t)row * D + t] = (char)(int)a;
    g_qb[(size_t)row * D + t] = (char)(int)b;
}

__device__ __forceinline__ void lse_combine(float& m, float& s, float m2, float s2) {
    const float M = fmaxf(m, m2);
    if (M == -CUDART_INF_F) return;
    s = s * __expf(m - M) + s2 * __expf(m2 - M);
    m = M;
}

// ---------------------------------------------------------------------------
// Kernel 2: one upper-triangle 128x128 tile; 8 warps (2x4), warp tile 64x32.
// 3 IMMA products per fragment pair; cp.async double-buffered smem.
// ---------------------------------------------------------------------------
__global__ __launch_bounds__(NTHREADS, 1)
void circle_tile_imma(const int* __restrict__ labels) {
    extern __shared__ char dsm[];
    __shared__ int   La[BM];
    __shared__ int   Lb[BN];
    __shared__ float rm[NTHREADS];
    __shared__ float rs[NTHREADS];

    const int tid  = threadIdx.x;
    const int wid  = tid >> 5;
    const int lane = tid & 31;
    const int wm   = wid & 1;          // 2 warp rows x 64
    const int wn   = wid >> 1;         // 4 warp cols x 32

    const uint32_t sb = smem_u32(dsm);

    int t = blockIdx.x, bi = 0, rowLen = NB;
    while (t >= rowLen) { t -= rowLen; rowLen--; bi++; }
    const int bj = bi + t;
    const float tileW = (bi == bj) ? 1.0f : 2.0f;
    const int rowBase = bi * BM, colBase = bj * BN;

    if (tid < BM) La[tid]      = labels[rowBase + tid];
    else          Lb[tid - BM] = labels[colBase + (tid - BM)];

    int acc_aa[4][4][4];   // q^2 scale
    int acc_x [4][4][4];   // q^3 scale (a.b' + b.a')
    #pragma unroll
    for (int mi = 0; mi < 4; mi++)
        #pragma unroll
        for (int ni = 0; ni < 4; ni++)
            #pragma unroll
            for (int e = 0; e < 4; e++) { acc_aa[mi][ni][e] = 0; acc_x[mi][ni][e] = 0; }

    // stage chunk c into stage-buffer sbuf (4 sub-buffers: Aa, Ab, Ba, Bb)
    auto stage = [&](int c, int sbuf) {
        const uint32_t base = sb + (uint32_t)sbuf * STAGE_B;
        #pragma unroll
        for (int it = 0; it < 8; it++) {
            const int idx = tid + it * NTHREADS;
            const int buf = idx >> 9;            // 512 segs per buffer
            const int v   = idx & 511;
            const int r   = v >> 2;
            const int seg = v & 3;
            const int grow = ((buf < 2) ? rowBase : colBase) + r;
            const char* gp = ((buf & 1) ? g_qb : g_qa) + (size_t)grow * D_DIM + c * CHK + seg * 16;
            cpasync16(base + (uint32_t)buf * BUF_B + (uint32_t)(r * STRIDE + seg * 16), gp);
        }
        CP_COMMIT();
    };

    // per-lane ldmatrix row/byte offsets (b16 view of int8 data)
    const int arow = (lane & 7) + ((lane >> 3) & 1) * 8;
    const int acol = (lane >> 4) * 16;             // byte offset 0/16
    const int brow = lane & 7;
    const int bcol = ((lane >> 3) & 1) * 16;       // byte offset 0/16

    stage(0, 0);
    for (int c = 0; c < NCH; c++) {
        if (c < NCH - 1) { stage(c + 1, (c + 1) & 1); CP_WAIT1(); }
        else             { CP_WAIT0(); }
        __syncthreads();

        const uint32_t S  = sb + (uint32_t)(c & 1) * STAGE_B;
        const uint32_t Aa = S, Ab = S + BUF_B, Ba = S + 2 * BUF_B, Bb = S + 3 * BUF_B;

        #pragma unroll
        for (int ks = 0; ks < CHK / 32; ks++) {
            const int k0 = ks * 32;
            uint32_t afa[4][4], afb[4][4], bfa[4][2], bfb[4][2];
            #pragma unroll
            for (int mi = 0; mi < 4; mi++) {
                const uint32_t ro = (uint32_t)((wm * 64 + mi * 16 + arow) * STRIDE + k0 + acol);
                ldm_x4(afa[mi], Aa + ro);
                ldm_x4(afb[mi], Ab + ro);
            }
            #pragma unroll
            for (int ni = 0; ni < 4; ni++) {
                const uint32_t ro = (uint32_t)((wn * 32 + ni * 8 + brow) * STRIDE + k0 + bcol);
                ldm_x2(bfa[ni], Ba + ro);
                ldm_x2(bfb[ni], Bb + ro);
            }
            #pragma unroll
            for (int mi = 0; mi < 4; mi++)
                #pragma unroll
                for (int ni = 0; ni < 4; ni++) {
                    mma_s8(acc_aa[mi][ni], afa[mi], bfa[ni]);   // a . a'
                    mma_s8(acc_x [mi][ni], afa[mi], bfb[ni]);   // a . b'
                    mma_s8(acc_x [mi][ni], afb[mi], bfa[ni]);   // b . a'
                }
        }
        __syncthreads();   // all reads of this stage done before restage at c+2
    }

    // ---- fused epilogue on register fragments ----
    int liA[8], ljB[8];
    #pragma unroll
    for (int mi = 0; mi < 4; mi++) {
        liA[mi * 2]     = La[wm * 64 + mi * 16 + (lane >> 2)];
        liA[mi * 2 + 1] = La[wm * 64 + mi * 16 + (lane >> 2) + 8];
    }
    #pragma unroll
    for (int ni = 0; ni < 4; ni++) {
        ljB[ni * 2]     = Lb[wn * 32 + ni * 8 + (lane & 3) * 2];
        ljB[ni * 2 + 1] = Lb[wn * 32 + ni * 8 + (lane & 3) * 2 + 1];
    }

    float lg[4][4][4];
    float mp = -CUDART_INF_F, mn = -CUDART_INF_F;
    #pragma unroll
    for (int mi = 0; mi < 4; mi++)
        #pragma unroll
        for (int ni = 0; ni < 4; ni++)
            #pragma unroll
            for (int e = 0; e < 4; e++) {
                const int row = wm * 64 + mi * 16 + (lane >> 2) + (e >> 1) * 8;
                const int col = wn * 32 + ni * 8 + (lane & 3) * 2 + (e & 1);
                const float s = Q2F * (float)acc_aa[mi][ni][e] + Q3F * (float)acc_x[mi][ni][e];
                const bool pos = (liA[mi * 2 + (e >> 1)] == ljB[ni * 2 + (e & 1)]);
                const float lp = -GAMMA * fmaxf(OPT_P - s, 0.f) * (s - DELTA_P);
                const float ln =  GAMMA * fmaxf(s + OPT_N, 0.f) * (s - DELTA_N);
                float l = pos ? lp : ln;
                if (pos && (rowBase + row) == (colBase + col)) l = -CUDART_INF_F;
                if (pos) mp = fmaxf(mp, l); else mn = fmaxf(mn, l);
                lg[mi][ni][e] = l;
            }

    const float mpu = (mp < -1e37f) ? 0.f : mp;
    const float mnu = (mn < -1e37f) ? 0.f : mn;
    float sp = 0.f, sn = 0.f;
    #pragma unroll
    for (int mi = 0; mi < 4; mi++)
        #pragma unroll
        for (int ni = 0; ni < 4; ni++)
            #pragma unroll
            for (int e = 0; e < 4; e++) {
                const bool pos = (liA[mi * 2 + (e >> 1)] == ljB[ni * 2 + (e & 1)]);
                const float ex = __expf(lg[mi][ni][e] - (pos ? mpu : mnu));
                if (pos) sp += ex; else sn += ex;
            }
    sp *= tileW; sn *= tileW;

    const int bid = blockIdx.x;
    rm[tid] = mp; rs[tid] = sp; __syncthreads();
    for (int off = NTHREADS / 2; off > 0; off >>= 1) {
        if (tid < off) {
            float m = rm[tid], s = rs[tid];
            lse_combine(m, s, rm[tid + off], rs[tid + off]);
            rm[tid] = m; rs[tid] = s;
        }
        __syncthreads();
    }
    if (tid == 0) { g_part[bid * 4 + 0] = rm[0]; g_part[bid * 4 + 1] = rs[0]; }
    __syncthreads();
    rm[tid] = mn; rs[tid] = sn; __syncthreads();
    for (int off = NTHREADS / 2; off > 0; off >>= 1) {
        if (tid < off) {
            float m = rm[tid], s = rs[tid];
            lse_combine(m, s, rm[tid + off], rs[tid + off]);
            rm[tid] = m; rs[tid] = s;
        }
        __syncthreads();
    }
    if (tid == 0) { g_part[bid * 4 + 2] = rm[0]; g_part[bid * 4 + 3] = rs[0]; }
}

// ---------------------------------------------------------------------------
// Kernel 3: combine partials, softplus, write scalar.
// ---------------------------------------------------------------------------
__global__ void finalize_kernel(float* __restrict__ out, int nPart) {
    const int t = threadIdx.x;
    float mp = -CUDART_INF_F, sp = 0.f, mn = -CUDART_INF_F, sn = 0.f;
    for (int i = t; i < nPart; i += blockDim.x) {
        lse_combine(mp, sp, g_part[i * 4 + 0], g_part[i * 4 + 1]);
        lse_combine(mn, sn, g_part[i * 4 + 2], g_part[i * 4 + 3]);
    }
    __shared__ float rm[256], rs[256];
    __shared__ float lse_p;
    rm[t] = mp; rs[t] = sp; __syncthreads();
    for (int off = 128; off > 0; off >>= 1) {
        if (t < off) {
            float m = rm[t], s = rs[t];
            lse_combine(m, s, rm[t + off], rs[t + off]);
            rm[t] = m; rs[t] = s;
        }
        __syncthreads();
    }
    if (t == 0) lse_p = rm[0] + logf(rs[0]);
    __syncthreads();
    rm[t] = mn; rs[t] = sn; __syncthreads();
    for (int off = 128; off > 0; off >>= 1) {
        if (t < off) {
            float m = rm[t], s = rs[t];
            lse_combine(m, s, rm[t + off], rs[t + off]);
            rm[t] = m; rs[t] = s;
        }
        __syncthreads();
    }
    if (t == 0) {
        const float x = lse_p + rm[0] + logf(rs[0]);
        out[0] = (x > 20.f) ? x : log1pf(expf(x));
    }
}

// ---------------------------------------------------------------------------
extern "C" void kernel_launch(void* const* d_in, const int* in_sizes, int n_in,
                              void* d_out, int out_size) {
    const float* emb    = (const float*)d_in[0];
    const int*   labels = (const int*)d_in[1];
    float*       out    = (float*)d_out;

    const int B = in_sizes[1];            // 8192
    const int D = in_sizes[0] / B;        // 256
    const int dyn = 2 * STAGE_B;          // 81920 bytes

    cudaFuncSetAttribute(circle_tile_imma, cudaFuncAttributeMaxDynamicSharedMemorySize, dyn);

    quantize_kernel<<<B, D>>>(emb, D);
    circle_tile_imma<<<NTILES, NTHREADS, dyn>>>(labels);
    finalize_kernel<<<1, 256>>>(out, NTILES);
}

// round 7
// speedup vs baseline: 6.1308x; 1.2562x over previous
#include <cuda_runtime.h>
#include <cuda_fp16.h>
#include <math.h>
#include <math_constants.h>
#include <stdint.h>

// ---------------------------------------------------------------------------
// CircleLoss round 6: single-product fp16 mma.sync GEMM + fused masked LSE.
//   Legacy mma on sm_100 is MAC-capped (~512 MAC/cyc/SM) independent of dtype,
//   so we minimize MACs: sim = fp16(x) . fp16(x)^T  (one product, fp32 accum).
//   sim err rms ~2e-5 -> output rel err ~1e-4 (threshold 1e-3).
//   Upper-triangle tiles; off-diagonal sum-exp doubled (exact).
// ---------------------------------------------------------------------------

#define N_MAX    8192
#define D_DIM    256
#define BM       128
#define BN       128
#define NB       (N_MAX / BM)          // 64
#define NTILES   (NB * (NB + 1) / 2)   // 2080
#define NTHREADS 256
#define CHK      64                    // K-chunk (fp16 elems)
#define NCH      (D_DIM / CHK)         // 4
#define STRIDE   144                   // smem row stride bytes (128 + 16 pad)
#define BUF_B    (BM * STRIDE)         // 18432 per buffer
#define STAGE_B  (2 * BUF_B)           // A, B
#define GAMMA    256.0f
#define DELTA_P  0.75f
#define DELTA_N  0.25f
#define OPT_P    1.25f
#define OPT_N    0.25f

__device__ __half g_xh[(size_t)N_MAX * D_DIM];   // 4 MB fp16 normalized
__device__ float  g_part[NTILES * 4];

__device__ __forceinline__ uint32_t smem_u32(const void* p) {
    uint32_t a;
    asm("{ .reg .u64 t; cvta.to.shared.u64 t, %1; cvt.u32.u64 %0, t; }" : "=r"(a) : "l"(p));
    return a;
}
__device__ __forceinline__ void ldm_x4(uint32_t* f, uint32_t addr) {
    asm volatile("ldmatrix.sync.aligned.m8n8.x4.shared.b16 {%0,%1,%2,%3}, [%4];"
                 : "=r"(f[0]), "=r"(f[1]), "=r"(f[2]), "=r"(f[3]) : "r"(addr));
}
__device__ __forceinline__ void ldm_x2(uint32_t* f, uint32_t addr) {
    asm volatile("ldmatrix.sync.aligned.m8n8.x2.shared.b16 {%0,%1}, [%2];"
                 : "=r"(f[0]), "=r"(f[1]) : "r"(addr));
}
__device__ __forceinline__ void mma_f16(float* d, const uint32_t* a, const uint32_t* b) {
    asm volatile("mma.sync.aligned.m16n8k16.row.col.f32.f16.f16.f32 "
                 "{%0,%1,%2,%3}, {%4,%5,%6,%7}, {%8,%9}, {%0,%1,%2,%3};"
                 : "+f"(d[0]), "+f"(d[1]), "+f"(d[2]), "+f"(d[3])
                 : "r"(a[0]), "r"(a[1]), "r"(a[2]), "r"(a[3]), "r"(b[0]), "r"(b[1]));
}
__device__ __forceinline__ void cpasync16(uint32_t saddr, const void* g) {
    asm volatile("cp.async.cg.shared.global [%0], [%1], 16;" :: "r"(saddr), "l"(g) : "memory");
}
#define CP_COMMIT() asm volatile("cp.async.commit_group;" ::: "memory")
#define CP_WAIT1()  asm volatile("cp.async.wait_group 1;" ::: "memory")
#define CP_WAIT0()  asm volatile("cp.async.wait_group 0;" ::: "memory")

// ---------------------------------------------------------------------------
// Kernel 1: L2-normalize + fp16 convert. One warp per row, 8 rows/block.
// ---------------------------------------------------------------------------
__global__ void normalize_kernel(const float* __restrict__ e) {
    const int wid  = threadIdx.x >> 5;
    const int lane = threadIdx.x & 31;
    const int row  = blockIdx.x * 8 + wid;
    const float4* rp = (const float4*)(e + (size_t)row * D_DIM);
    const float4 v0 = rp[lane * 2];
    const float4 v1 = rp[lane * 2 + 1];
    float ss = v0.x * v0.x + v0.y * v0.y + v0.z * v0.z + v0.w * v0.w
             + v1.x * v1.x + v1.y * v1.y + v1.z * v1.z + v1.w * v1.w;
    #pragma unroll
    for (int o = 16; o > 0; o >>= 1) ss += __shfl_xor_sync(0xffffffffu, ss, o);
    const float inv = 1.0f / fmaxf(sqrtf(ss), 1e-12f);
    __half2 h[4];
    h[0] = __floats2half2_rn(v0.x * inv, v0.y * inv);
    h[1] = __floats2half2_rn(v0.z * inv, v0.w * inv);
    h[2] = __floats2half2_rn(v1.x * inv, v1.y * inv);
    h[3] = __floats2half2_rn(v1.z * inv, v1.w * inv);
    *(uint4*)(g_xh + (size_t)row * D_DIM + lane * 8) = *(const uint4*)h;
}

__device__ __forceinline__ void lse_combine(float& m, float& s, float m2, float s2) {
    const float M = fmaxf(m, m2);
    if (M == -CUDART_INF_F) return;
    s = s * __expf(m - M) + s2 * __expf(m2 - M);
    m = M;
}

// ---------------------------------------------------------------------------
// Kernel 2: one upper-triangle 128x128 tile; 8 warps (2x4), warp tile 64x32.
// Single fp16 MMA product; cp.async double-buffered smem.
// ---------------------------------------------------------------------------
__global__ __launch_bounds__(NTHREADS, 1)
void circle_tile_hmma(const int* __restrict__ labels) {
    extern __shared__ char dsm[];
    __shared__ int   La[BM];
    __shared__ int   Lb[BN];
    __shared__ float rm[NTHREADS];
    __shared__ float rs[NTHREADS];

    const int tid  = threadIdx.x;
    const int wid  = tid >> 5;
    const int lane = tid & 31;
    const int wm   = wid & 1;          // 2 warp rows x 64
    const int wn   = wid >> 1;         // 4 warp cols x 32

    const uint32_t sb = smem_u32(dsm);

    int t = blockIdx.x, bi = 0, rowLen = NB;
    while (t >= rowLen) { t -= rowLen; rowLen--; bi++; }
    const int bj = bi + t;
    const float tileW = (bi == bj) ? 1.0f : 2.0f;
    const int rowBase = bi * BM, colBase = bj * BN;

    if (tid < BM) La[tid]      = labels[rowBase + tid];
    else          Lb[tid - BM] = labels[colBase + (tid - BM)];

    float acc[4][4][4];
    #pragma unroll
    for (int mi = 0; mi < 4; mi++)
        #pragma unroll
        for (int ni = 0; ni < 4; ni++)
            #pragma unroll
            for (int e = 0; e < 4; e++) acc[mi][ni][e] = 0.f;

    // stage chunk c into stage sbuf: 2 buffers (A=rowBase, B=colBase),
    // each 128 rows x 128 bytes (64 fp16), 8 x 16B segs per row.
    auto stage = [&](int c, int sbuf) {
        const uint32_t base = sb + (uint32_t)sbuf * STAGE_B;
        #pragma unroll
        for (int it = 0; it < 8; it++) {
            const int idx = tid + it * NTHREADS;
            const int buf = idx >> 10;           // 1024 segs per buffer
            const int v   = idx & 1023;
            const int r   = v >> 3;
            const int seg = v & 7;
            const int grow = (buf ? colBase : rowBase) + r;
            const __half* gp = g_xh + (size_t)grow * D_DIM + c * CHK + seg * 8;
            cpasync16(base + (uint32_t)buf * BUF_B + (uint32_t)(r * STRIDE + seg * 16), gp);
        }
        CP_COMMIT();
    };

    // per-lane ldmatrix offsets (b16 elems)
    const int arow = (lane & 7) + ((lane >> 3) & 1) * 8;
    const int acol = (lane >> 4) * 8;
    const int brow = lane & 7;
    const int bcol = ((lane >> 3) & 1) * 8;

    stage(0, 0);
    for (int c = 0; c < NCH; c++) {
        if (c < NCH - 1) { stage(c + 1, (c + 1) & 1); CP_WAIT1(); }
        else             { CP_WAIT0(); }
        __syncthreads();

        const uint32_t S  = sb + (uint32_t)(c & 1) * STAGE_B;
        const uint32_t Sa = S, Sb = S + BUF_B;

        #pragma unroll
        for (int ks = 0; ks < CHK / 16; ks++) {
            const int k0 = ks * 16;
            uint32_t af[4][4], bf[4][2];
            #pragma unroll
            for (int mi = 0; mi < 4; mi++) {
                const uint32_t ro = (uint32_t)((wm * 64 + mi * 16 + arow) * STRIDE + (k0 + acol) * 2);
                ldm_x4(af[mi], Sa + ro);
            }
            #pragma unroll
            for (int ni = 0; ni < 4; ni++) {
                const uint32_t ro = (uint32_t)((wn * 32 + ni * 8 + brow) * STRIDE + (k0 + bcol) * 2);
                ldm_x2(bf[ni], Sb + ro);
            }
            #pragma unroll
            for (int mi = 0; mi < 4; mi++)
                #pragma unroll
                for (int ni = 0; ni < 4; ni++)
                    mma_f16(acc[mi][ni], af[mi], bf[ni]);
        }
        __syncthreads();   // reads done before this stage is overwritten (c+2)
    }

    // ---- fused epilogue on register fragments (logits written in place) ----
    int liA[8], ljB[8];
    #pragma unroll
    for (int mi = 0; mi < 4; mi++) {
        liA[mi * 2]     = La[wm * 64 + mi * 16 + (lane >> 2)];
        liA[mi * 2 + 1] = La[wm * 64 + mi * 16 + (lane >> 2) + 8];
    }
    #pragma unroll
    for (int ni = 0; ni < 4; ni++) {
        ljB[ni * 2]     = Lb[wn * 32 + ni * 8 + (lane & 3) * 2];
        ljB[ni * 2 + 1] = Lb[wn * 32 + ni * 8 + (lane & 3) * 2 + 1];
    }

    float mp = -CUDART_INF_F, mn = -CUDART_INF_F;
    #pragma unroll
    for (int mi = 0; mi < 4; mi++)
        #pragma unroll
        for (int ni = 0; ni < 4; ni++)
            #pragma unroll
            for (int e = 0; e < 4; e++) {
                const int row = wm * 64 + mi * 16 + (lane >> 2) + (e >> 1) * 8;
                const int col = wn * 32 + ni * 8 + (lane & 3) * 2 + (e & 1);
                const float s = acc[mi][ni][e];
                const bool pos = (liA[mi * 2 + (e >> 1)] == ljB[ni * 2 + (e & 1)]);
                const float lp = -GAMMA * fmaxf(OPT_P - s, 0.f) * (s - DELTA_P);
                const float ln =  GAMMA * fmaxf(s + OPT_N, 0.f) * (s - DELTA_N);
                float l = pos ? lp : ln;
                if (pos && (rowBase + row) == (colBase + col)) l = -CUDART_INF_F;
                if (pos) mp = fmaxf(mp, l); else mn = fmaxf(mn, l);
                acc[mi][ni][e] = l;
            }

    const float mpu = (mp < -1e37f) ? 0.f : mp;
    const float mnu = (mn < -1e37f) ? 0.f : mn;
    float sp = 0.f, sn = 0.f;
    #pragma unroll
    for (int mi = 0; mi < 4; mi++)
        #pragma unroll
        for (int ni = 0; ni < 4; ni++)
            #pragma unroll
            for (int e = 0; e < 4; e++) {
                const bool pos = (liA[mi * 2 + (e >> 1)] == ljB[ni * 2 + (e & 1)]);
                const float ex = __expf(acc[mi][ni][e] - (pos ? mpu : mnu));
                if (pos) sp += ex; else sn += ex;
            }
    sp *= tileW; sn *= tileW;

    const int bid = blockIdx.x;
    rm[tid] = mp; rs[tid] = sp; __syncthreads();
    for (int off = NTHREADS / 2; off > 0; off >>= 1) {
        if (tid < off) {
            float m = rm[tid], s = rs[tid];
            lse_combine(m, s, rm[tid + off], rs[tid + off]);
            rm[tid] = m; rs[tid] = s;
        }
        __syncthreads();
    }
    if (tid == 0) { g_part[bid * 4 + 0] = rm[0]; g_part[bid * 4 + 1] = rs[0]; }
    __syncthreads();
    rm[tid] = mn; rs[tid] = sn; __syncthreads();
    for (int off = NTHREADS / 2; off > 0; off >>= 1) {
        if (tid < off) {
            float m = rm[tid], s = rs[tid];
            lse_combine(m, s, rm[tid + off], rs[tid + off]);
            rm[tid] = m; rs[tid] = s;
        }
        __syncthreads();
    }
    if (tid == 0) { g_part[bid * 4 + 2] = rm[0]; g_part[bid * 4 + 3] = rs[0]; }
}

// ---------------------------------------------------------------------------
// Kernel 3: combine partials, softplus, write scalar.
// ---------------------------------------------------------------------------
__global__ void finalize_kernel(float* __restrict__ out, int nPart) {
    const int t = threadIdx.x;
    float mp = -CUDART_INF_F, sp = 0.f, mn = -CUDART_INF_F, sn = 0.f;
    for (int i = t; i < nPart; i += blockDim.x) {
        lse_combine(mp, sp, g_part[i * 4 + 0], g_part[i * 4 + 1]);
        lse_combine(mn, sn, g_part[i * 4 + 2], g_part[i * 4 + 3]);
    }
    __shared__ float rm[256], rs[256];
    __shared__ float lse_p;
    rm[t] = mp; rs[t] = sp; __syncthreads();
    for (int off = 128; off > 0; off >>= 1) {
        if (t < off) {
            float m = rm[t], s = rs[t];
            lse_combine(m, s, rm[t + off], rs[t + off]);
            rm[t] = m; rs[t] = s;
        }
        __syncthreads();
    }
    if (t == 0) lse_p = rm[0] + logf(rs[0]);
    __syncthreads();
    rm[t] = mn; rs[t] = sn; __syncthreads();
    for (int off = 128; off > 0; off >>= 1) {
        if (t < off) {
            float m = rm[t], s = rs[t];
            lse_combine(m, s, rm[t + off], rs[t + off]);
            rm[t] = m; rs[t] = s;
        }
        __syncthreads();
    }
    if (t == 0) {
        const float x = lse_p + rm[0] + logf(rs[0]);
        out[0] = (x > 20.f) ? x : log1pf(expf(x));
    }
}

// ---------------------------------------------------------------------------
extern "C" void kernel_launch(void* const* d_in, const int* in_sizes, int n_in,
                              void* d_out, int out_size) {
    const float* emb    = (const float*)d_in[0];
    const int*   labels = (const int*)d_in[1];
    float*       out    = (float*)d_out;

    const int B = in_sizes[1];            // 8192
    const int dyn = 2 * STAGE_B;          // 73728 bytes

    cudaFuncSetAttribute(circle_tile_hmma, cudaFuncAttributeMaxDynamicSharedMemorySize, dyn);

    normalize_kernel<<<B / 8, 256>>>(emb);
    circle_tile_hmma<<<NTILES, NTHREADS, dyn>>>(labels);
    finalize_kernel<<<1, 256>>>(out, NTILES);
}

// round 8
// speedup vs baseline: 8.0616x; 1.3149x over previous
#include <cuda_runtime.h>
#include <cuda_fp16.h>
#include <math.h>
#include <math_constants.h>
#include <stdint.h>

// ---------------------------------------------------------------------------
// CircleLoss round 7: fp16 single-product mma.sync + fused LSE.
//   Model: legacy mma.sync on sm_100 issues at ~32 cyc/instr per SMSP
//   regardless of dtype/shape -> f16 m16n8k16 MMA floor ~118us.
//   This round: 2 CTAs/SM (overlap epilogue/staging with other CTA's MMA)
//   + shuffle-based LSE reduction (2 syncs instead of 17).
// ---------------------------------------------------------------------------

#define N_MAX    8192
#define D_DIM    256
#define BM       128
#define BN       128
#define NB       (N_MAX / BM)          // 64
#define NTILES   (NB * (NB + 1) / 2)   // 2080
#define NTHREADS 256
#define CHK      64                    // K-chunk (fp16 elems)
#define NCH      (D_DIM / CHK)         // 4
#define STRIDE   144                   // smem row stride bytes (128 + 16 pad)
#define BUF_B    (BM * STRIDE)         // 18432 per buffer
#define STAGE_B  (2 * BUF_B)           // A, B
#define GAMMA    256.0f
#define DELTA_P  0.75f
#define DELTA_N  0.25f
#define OPT_P    1.25f
#define OPT_N    0.25f

__device__ __half g_xh[(size_t)N_MAX * D_DIM];   // 4 MB fp16 normalized
__device__ float  g_part[NTILES * 4];

__device__ __forceinline__ uint32_t smem_u32(const void* p) {
    uint32_t a;
    asm("{ .reg .u64 t; cvta.to.shared.u64 t, %1; cvt.u32.u64 %0, t; }" : "=r"(a) : "l"(p));
    return a;
}
__device__ __forceinline__ void ldm_x4(uint32_t* f, uint32_t addr) {
    asm volatile("ldmatrix.sync.aligned.m8n8.x4.shared.b16 {%0,%1,%2,%3}, [%4];"
                 : "=r"(f[0]), "=r"(f[1]), "=r"(f[2]), "=r"(f[3]) : "r"(addr));
}
__device__ __forceinline__ void ldm_x2(uint32_t* f, uint32_t addr) {
    asm volatile("ldmatrix.sync.aligned.m8n8.x2.shared.b16 {%0,%1}, [%2];"
                 : "=r"(f[0]), "=r"(f[1]) : "r"(addr));
}
__device__ __forceinline__ void mma_f16(float* d, const uint32_t* a, const uint32_t* b) {
    asm volatile("mma.sync.aligned.m16n8k16.row.col.f32.f16.f16.f32 "
                 "{%0,%1,%2,%3}, {%4,%5,%6,%7}, {%8,%9}, {%0,%1,%2,%3};"
                 : "+f"(d[0]), "+f"(d[1]), "+f"(d[2]), "+f"(d[3])
                 : "r"(a[0]), "r"(a[1]), "r"(a[2]), "r"(a[3]), "r"(b[0]), "r"(b[1]));
}
__device__ __forceinline__ void cpasync16(uint32_t saddr, const void* g) {
    asm volatile("cp.async.cg.shared.global [%0], [%1], 16;" :: "r"(saddr), "l"(g) : "memory");
}
#define CP_COMMIT() asm volatile("cp.async.commit_group;" ::: "memory")
#define CP_WAIT1()  asm volatile("cp.async.wait_group 1;" ::: "memory")
#define CP_WAIT0()  asm volatile("cp.async.wait_group 0;" ::: "memory")

// ---------------------------------------------------------------------------
// Kernel 1: L2-normalize + fp16 convert. One warp per row, 8 rows/block.
// ---------------------------------------------------------------------------
__global__ void normalize_kernel(const float* __restrict__ e) {
    const int wid  = threadIdx.x >> 5;
    const int lane = threadIdx.x & 31;
    const int row  = blockIdx.x * 8 + wid;
    const float4* rp = (const float4*)(e + (size_t)row * D_DIM);
    const float4 v0 = rp[lane * 2];
    const float4 v1 = rp[lane * 2 + 1];
    float ss = v0.x * v0.x + v0.y * v0.y + v0.z * v0.z + v0.w * v0.w
             + v1.x * v1.x + v1.y * v1.y + v1.z * v1.z + v1.w * v1.w;
    #pragma unroll
    for (int o = 16; o > 0; o >>= 1) ss += __shfl_xor_sync(0xffffffffu, ss, o);
    const float inv = 1.0f / fmaxf(sqrtf(ss), 1e-12f);
    __half2 h[4];
    h[0] = __floats2half2_rn(v0.x * inv, v0.y * inv);
    h[1] = __floats2half2_rn(v0.z * inv, v0.w * inv);
    h[2] = __floats2half2_rn(v1.x * inv, v1.y * inv);
    h[3] = __floats2half2_rn(v1.z * inv, v1.w * inv);
    *(uint4*)(g_xh + (size_t)row * D_DIM + lane * 8) = *(const uint4*)h;
}

__device__ __forceinline__ void lse_combine(float& m, float& s, float m2, float s2) {
    const float M = fmaxf(m, m2);
    if (M == -CUDART_INF_F) return;
    s = s * __expf(m - M) + s2 * __expf(m2 - M);
    m = M;
}

// ---------------------------------------------------------------------------
// Kernel 2: one upper-triangle 128x128 tile; 8 warps (2x4), warp tile 64x32.
// Single fp16 MMA product; cp.async double-buffered smem; 2 CTAs/SM.
// ---------------------------------------------------------------------------
__global__ __launch_bounds__(NTHREADS, 2)
void circle_tile_hmma(const int* __restrict__ labels) {
    extern __shared__ char dsm[];
    __shared__ int   La[BM];
    __shared__ int   Lb[BN];
    __shared__ float wred[8][4];       // per-warp (mp,sp,mn,sn)

    const int tid  = threadIdx.x;
    const int wid  = tid >> 5;
    const int lane = tid & 31;
    const int wm   = wid & 1;          // 2 warp rows x 64
    const int wn   = wid >> 1;         // 4 warp cols x 32

    const uint32_t sb = smem_u32(dsm);

    int t = blockIdx.x, bi = 0, rowLen = NB;
    while (t >= rowLen) { t -= rowLen; rowLen--; bi++; }
    const int bj = bi + t;
    const float tileW = (bi == bj) ? 1.0f : 2.0f;
    const int rowBase = bi * BM, colBase = bj * BN;

    if (tid < BM) La[tid]      = labels[rowBase + tid];
    else          Lb[tid - BM] = labels[colBase + (tid - BM)];

    float acc[4][4][4];
    #pragma unroll
    for (int mi = 0; mi < 4; mi++)
        #pragma unroll
        for (int ni = 0; ni < 4; ni++)
            #pragma unroll
            for (int e = 0; e < 4; e++) acc[mi][ni][e] = 0.f;

    auto stage = [&](int c, int sbuf) {
        const uint32_t base = sb + (uint32_t)sbuf * STAGE_B;
        #pragma unroll
        for (int it = 0; it < 8; it++) {
            const int idx = tid + it * NTHREADS;
            const int buf = idx >> 10;
            const int v   = idx & 1023;
            const int r   = v >> 3;
            const int seg = v & 7;
            const int grow = (buf ? colBase : rowBase) + r;
            const __half* gp = g_xh + (size_t)grow * D_DIM + c * CHK + seg * 8;
            cpasync16(base + (uint32_t)buf * BUF_B + (uint32_t)(r * STRIDE + seg * 16), gp);
        }
        CP_COMMIT();
    };

    const int arow = (lane & 7) + ((lane >> 3) & 1) * 8;
    const int acol = (lane >> 4) * 8;
    const int brow = lane & 7;
    const int bcol = ((lane >> 3) & 1) * 8;

    stage(0, 0);
    for (int c = 0; c < NCH; c++) {
        if (c < NCH - 1) { stage(c + 1, (c + 1) & 1); CP_WAIT1(); }
        else             { CP_WAIT0(); }
        __syncthreads();

        const uint32_t S  = sb + (uint32_t)(c & 1) * STAGE_B;
        const uint32_t Sa = S, Sb = S + BUF_B;

        #pragma unroll
        for (int ks = 0; ks < CHK / 16; ks++) {
            const int k0 = ks * 16;
            uint32_t af[4][4], bf[4][2];
            #pragma unroll
            for (int mi = 0; mi < 4; mi++) {
                const uint32_t ro = (uint32_t)((wm * 64 + mi * 16 + arow) * STRIDE + (k0 + acol) * 2);
                ldm_x4(af[mi], Sa + ro);
            }
            #pragma unroll
            for (int ni = 0; ni < 4; ni++) {
                const uint32_t ro = (uint32_t)((wn * 32 + ni * 8 + brow) * STRIDE + (k0 + bcol) * 2);
                ldm_x2(bf[ni], Sb + ro);
            }
            #pragma unroll
            for (int mi = 0; mi < 4; mi++)
                #pragma unroll
                for (int ni = 0; ni < 4; ni++)
                    mma_f16(acc[mi][ni], af[mi], bf[ni]);
        }
        __syncthreads();
    }

    // ---- fused epilogue on register fragments ----
    int liA[8], ljB[8];
    #pragma unroll
    for (int mi = 0; mi < 4; mi++) {
        liA[mi * 2]     = La[wm * 64 + mi * 16 + (lane >> 2)];
        liA[mi * 2 + 1] = La[wm * 64 + mi * 16 + (lane >> 2) + 8];
    }
    #pragma unroll
    for (int ni = 0; ni < 4; ni++) {
        ljB[ni * 2]     = Lb[wn * 32 + ni * 8 + (lane & 3) * 2];
        ljB[ni * 2 + 1] = Lb[wn * 32 + ni * 8 + (lane & 3) * 2 + 1];
    }

    float mp = -CUDART_INF_F, mn = -CUDART_INF_F;
    #pragma unroll
    for (int mi = 0; mi < 4; mi++)
        #pragma unroll
        for (int ni = 0; ni < 4; ni++)
            #pragma unroll
            for (int e = 0; e < 4; e++) {
                const int row = wm * 64 + mi * 16 + (lane >> 2) + (e >> 1) * 8;
                const int col = wn * 32 + ni * 8 + (lane & 3) * 2 + (e & 1);
                const float s = acc[mi][ni][e];
                const bool pos = (liA[mi * 2 + (e >> 1)] == ljB[ni * 2 + (e & 1)]);
                const float lp = -GAMMA * fmaxf(OPT_P - s, 0.f) * (s - DELTA_P);
                const float ln =  GAMMA * fmaxf(s + OPT_N, 0.f) * (s - DELTA_N);
                float l = pos ? lp : ln;
                if (pos && (rowBase + row) == (colBase + col)) l = -CUDART_INF_F;
                if (pos) mp = fmaxf(mp, l); else mn = fmaxf(mn, l);
                acc[mi][ni][e] = l;
            }

    const float mpu = (mp < -1e37f) ? 0.f : mp;
    const float mnu = (mn < -1e37f) ? 0.f : mn;
    float sp = 0.f, sn = 0.f;
    #pragma unroll
    for (int mi = 0; mi < 4; mi++)
        #pragma unroll
        for (int ni = 0; ni < 4; ni++)
            #pragma unroll
            for (int e = 0; e < 4; e++) {
                const bool pos = (liA[mi * 2 + (e >> 1)] == ljB[ni * 2 + (e & 1)]);
                const float ex = __expf(acc[mi][ni][e] - (pos ? mpu : mnu));
                if (pos) sp += ex; else sn += ex;
            }
    sp *= tileW; sn *= tileW;

    // warp shuffle LSE reduction (5 steps, 4 values)
    #pragma unroll
    for (int o = 16; o > 0; o >>= 1) {
        const float mp2 = __shfl_xor_sync(0xffffffffu, mp, o);
        const float sp2 = __shfl_xor_sync(0xffffffffu, sp, o);
        const float mn2 = __shfl_xor_sync(0xffffffffu, mn, o);
        const float sn2 = __shfl_xor_sync(0xffffffffu, sn, o);
        lse_combine(mp, sp, mp2, sp2);
        lse_combine(mn, sn, mn2, sn2);
    }
    if (lane == 0) {
        wred[wid][0] = mp; wred[wid][1] = sp;
        wred[wid][2] = mn; wred[wid][3] = sn;
    }
    __syncthreads();
    if (wid == 0 && lane == 0) {
        float Mp = wred[0][0], Sp = wred[0][1], Mn = wred[0][2], Sn = wred[0][3];
        #pragma unroll
        for (int w = 1; w < 8; w++) {
            lse_combine(Mp, Sp, wred[w][0], wred[w][1]);
            lse_combine(Mn, Sn, wred[w][2], wred[w][3]);
        }
        const int bid = blockIdx.x;
        g_part[bid * 4 + 0] = Mp; g_part[bid * 4 + 1] = Sp;
        g_part[bid * 4 + 2] = Mn; g_part[bid * 4 + 3] = Sn;
    }
}

// ---------------------------------------------------------------------------
// Kernel 3: combine partials, softplus, write scalar.
// ---------------------------------------------------------------------------
__global__ void finalize_kernel(float* __restrict__ out, int nPart) {
    const int t = threadIdx.x;
    float mp = -CUDART_INF_F, sp = 0.f, mn = -CUDART_INF_F, sn = 0.f;
    for (int i = t; i < nPart; i += blockDim.x) {
        lse_combine(mp, sp, g_part[i * 4 + 0], g_part[i * 4 + 1]);
        lse_combine(mn, sn, g_part[i * 4 + 2], g_part[i * 4 + 3]);
    }
    __shared__ float rm[256], rs[256];
    __shared__ float lse_p;
    rm[t] = mp; rs[t] = sp; __syncthreads();
    for (int off = 128; off > 0; off >>= 1) {
        if (t < off) {
            float m = rm[t], s = rs[t];
            lse_combine(m, s, rm[t + off], rs[t + off]);
            rm[t] = m; rs[t] = s;
        }
        __syncthreads();
    }
    if (t == 0) lse_p = rm[0] + logf(rs[0]);
    __syncthreads();
    rm[t] = mn; rs[t] = sn; __syncthreads();
    for (int off = 128; off > 0; off >>= 1) {
        if (t < off) {
            float m = rm[t], s = rs[t];
            lse_combine(m, s, rm[t + off], rs[t + off]);
            rm[t] = m; rs[t] = s;
        }
        __syncthreads();
    }
    if (t == 0) {
        const float x = lse_p + rm[0] + logf(rs[0]);
        out[0] = (x > 20.f) ? x : log1pf(expf(x));
    }
}

// ---------------------------------------------------------------------------
extern "C" void kernel_launch(void* const* d_in, const int* in_sizes, int n_in,
                              void* d_out, int out_size) {
    const float* emb    = (const float*)d_in[0];
    const int*   labels = (const int*)d_in[1];
    float*       out    = (float*)d_out;

    const int B = in_sizes[1];            // 8192
    const int dyn = 2 * STAGE_B;          // 73728 bytes

    cudaFuncSetAttribute(circle_tile_hmma, cudaFuncAttributeMaxDynamicSharedMemorySize, dyn);

    normalize_kernel<<<B / 8, 256>>>(emb);
    circle_tile_hmma<<<NTILES, NTHREADS, dyn>>>(labels);
    finalize_kernel<<<1, 256>>>(out, NTILES);
}